// round 2
// baseline (speedup 1.0000x reference)
#include <cuda_runtime.h>

// ---------------------------------------------------------------------------
// 2-layer LSTM (H=51), B=4096, T=1000 + 100 autoregressive steps.
// Batch is independent across the recurrence -> each block owns NB=28 batch
// elements and runs all 1100 steps with weights + state in shared memory.
//
// Per step (all threads participate in every phase, 6 __syncthreads):
//   stage x -> GEMM1 (k=52: 51 h1 + 1 x) -> cell update 1 ->
//   GEMM2 (k=104: 51 h1 + pad + 51 h2 + pad) -> cell update 2 -> output dot
//
// GEMM: state S[k][e] and weights W[k][g] are k-major; each thread owns a
// 4(g) x 4(e) register tile, float4 loads from shared, 16 FMA per k.
// ---------------------------------------------------------------------------

#define H       51
#define R4      204          // 4*H gate rows
#define RP      208          // padded gate rows (mult of 4)
#define TSTEPS  1000
#define FUT     100
#define NTOT    1100
#define BATCH   4096
#define NB      28           // batch elements per block
#define NBLK    147          // ceil(4096/28) -> 147*28 = 4116
#define BPAD    (NBLK * NB)  // 4116 padded batch for transposed input
#define NTH     384
#define K1      52           // layer1 k-dim: 51 h1 rows + 1 x row
#define K2      104          // layer2 k-dim: 51 h1 + 1 pad + 51 h2 + 1 pad
#define ETILES  7            // NB/4
#define GTILES  52           // RP/4
#define NGEMM   (ETILES * GTILES)  // 364 active GEMM threads
#define CELLS   (H * NB)     // 1428 cell updates per layer

// Transposed (and batch-padded) input: x_T[t][b]
__device__ float g_xT[TSTEPS * BPAD];

struct Smem {
    float W1[K1][RP];     // rows 0..50: Whh1^T, row 51: Wih1
    float W2[K2][RP];     // rows 0..50: Wih2^T, 51: 0, 52..102: Whh2^T, 103: 0
    float S[K2][NB];      // rows 0..50: h1, 51: x, 52..102: h2, 103: 0
    float G[RP][NB];      // gate pre-activations (reused by both layers)
    float c1[H][NB];
    float c2[H][NB];
    float bs1[R4];        // b_ih1 + b_hh1
    float bs2[R4];        // b_ih2 + b_hh2
    float wlin[H];
    float outbuf[NB];     // last output (feeds x during future phase)
    float blin;
};

__device__ __forceinline__ float sigf(float x) {
    return 1.0f / (1.0f + __expf(-x));
}
__device__ __forceinline__ float tanh_f(float x) {
    float e = __expf(-2.0f * fabsf(x));     // e in (0,1], overflow-safe
    float t = (1.0f - e) / (1.0f + e);
    return copysignf(t, x);
}

// Transpose inputs [B][T] -> g_xT[T][BPAD] (zero-fill padded batch rows).
__global__ void prep_kernel(const float* __restrict__ in) {
    int stride = gridDim.x * blockDim.x;
    for (int idx = blockIdx.x * blockDim.x + threadIdx.x;
         idx < BPAD * TSTEPS; idx += stride) {
        int b = idx / TSTEPS;
        int t = idx - b * TSTEPS;
        float v = (b < BATCH) ? in[idx] : 0.0f;   // in[b*T + t] == in[idx]
        g_xT[t * BPAD + b] = v;
    }
}

#define OUTER4(a0, a1, a2, a3, wv, hv)                                         \
    a0.x += wv.x * hv.x; a0.y += wv.x * hv.y; a0.z += wv.x * hv.z; a0.w += wv.x * hv.w; \
    a1.x += wv.y * hv.x; a1.y += wv.y * hv.y; a1.z += wv.y * hv.z; a1.w += wv.y * hv.w; \
    a2.x += wv.z * hv.x; a2.y += wv.z * hv.y; a2.z += wv.z * hv.z; a2.w += wv.z * hv.w; \
    a3.x += wv.w * hv.x; a3.y += wv.w * hv.y; a3.z += wv.w * hv.z; a3.w += wv.w * hv.w;

__global__ __launch_bounds__(NTH, 1)
void lstm_kernel(const float* __restrict__ Wih1, const float* __restrict__ Whh1,
                 const float* __restrict__ bih1, const float* __restrict__ bhh1,
                 const float* __restrict__ Wih2, const float* __restrict__ Whh2,
                 const float* __restrict__ bih2, const float* __restrict__ bhh2,
                 const float* __restrict__ Wlin, const float* __restrict__ blin,
                 float* __restrict__ out) {
    extern __shared__ unsigned char smraw[];
    Smem* sm = reinterpret_cast<Smem*>(smraw);
    const int tid = threadIdx.x;
    const int b0  = blockIdx.x * NB;

    // ---- one-time init: weights (transposed), biases, zero state ----
    for (int idx = tid; idx < K1 * RP; idx += NTH) {
        int k = idx / RP;
        int g = idx - k * RP;
        float v = 0.0f;
        if (g < R4) v = (k < H) ? Whh1[g * H + k] : Wih1[g];
        sm->W1[k][g] = v;
    }
    for (int idx = tid; idx < K2 * RP; idx += NTH) {
        int k = idx / RP;
        int g = idx - k * RP;
        float v = 0.0f;
        if (g < R4) {
            if (k < H)                    v = Wih2[g * H + k];
            else if (k >= 52 && k < 52+H) v = Whh2[g * H + (k - 52)];
        }
        sm->W2[k][g] = v;
    }
    for (int idx = tid; idx < R4; idx += NTH) {
        sm->bs1[idx] = bih1[idx] + bhh1[idx];
        sm->bs2[idx] = bih2[idx] + bhh2[idx];
    }
    for (int idx = tid; idx < H; idx += NTH) sm->wlin[idx] = Wlin[idx];
    if (tid == 0) sm->blin = blin[0];
    for (int idx = tid; idx < K2 * NB; idx += NTH) (&sm->S[0][0])[idx] = 0.0f;
    for (int idx = tid; idx < H * NB; idx += NTH) {
        (&sm->c1[0][0])[idx] = 0.0f;
        (&sm->c2[0][0])[idx] = 0.0f;
    }
    __syncthreads();

    const int  et4 = (tid % ETILES) * 4;
    const int  gt4 = (tid / ETILES) * 4;        // only valid when gemm_active
    const bool gemm_active = (tid < NGEMM);

    for (int t = 0; t < NTOT; ++t) {
        // ---- stage x(t) into S row 51 ----
        if (tid < NB) {
            float x = (t < TSTEPS) ? g_xT[t * BPAD + b0 + tid] : sm->outbuf[tid];
            sm->S[H][tid] = x;
        }
        __syncthreads();

        // ---- GEMM1: G[g][e] = sum_{k<52} W1[k][g] * S[k][e] ----
        if (gemm_active) {
            float4 a0 = {0,0,0,0}, a1 = {0,0,0,0}, a2 = {0,0,0,0}, a3 = {0,0,0,0};
            #pragma unroll 4
            for (int k = 0; k < K1; ++k) {
                float4 hv = *reinterpret_cast<const float4*>(&sm->S[k][et4]);
                float4 wv = *reinterpret_cast<const float4*>(&sm->W1[k][gt4]);
                OUTER4(a0, a1, a2, a3, wv, hv)
            }
            *reinterpret_cast<float4*>(&sm->G[gt4 + 0][et4]) = a0;
            *reinterpret_cast<float4*>(&sm->G[gt4 + 1][et4]) = a1;
            *reinterpret_cast<float4*>(&sm->G[gt4 + 2][et4]) = a2;
            *reinterpret_cast<float4*>(&sm->G[gt4 + 3][et4]) = a3;
        }
        __syncthreads();

        // ---- cell update layer 1: writes h1 into S rows 0..50 ----
        for (int c = tid; c < CELLS; c += NTH) {
            int k = c / NB;
            int e = c - k * NB;
            float gi = sm->G[k        ][e] + sm->bs1[k];
            float gf = sm->G[H   + k  ][e] + sm->bs1[H   + k];
            float gg = sm->G[2*H + k  ][e] + sm->bs1[2*H + k];
            float go = sm->G[3*H + k  ][e] + sm->bs1[3*H + k];
            float cc = sm->c1[k][e];
            float cn = sigf(gf) * cc + sigf(gi) * tanh_f(gg);
            float hn = sigf(go) * tanh_f(cn);
            sm->c1[k][e] = cn;
            sm->S[k][e]  = hn;
        }
        __syncthreads();

        // ---- GEMM2: k over [h1 (new); pad; h2 (old); pad] ----
        if (gemm_active) {
            float4 a0 = {0,0,0,0}, a1 = {0,0,0,0}, a2 = {0,0,0,0}, a3 = {0,0,0,0};
            #pragma unroll 4
            for (int k = 0; k < K2; ++k) {
                float4 hv = *reinterpret_cast<const float4*>(&sm->S[k][et4]);
                float4 wv = *reinterpret_cast<const float4*>(&sm->W2[k][gt4]);
                OUTER4(a0, a1, a2, a3, wv, hv)
            }
            *reinterpret_cast<float4*>(&sm->G[gt4 + 0][et4]) = a0;
            *reinterpret_cast<float4*>(&sm->G[gt4 + 1][et4]) = a1;
            *reinterpret_cast<float4*>(&sm->G[gt4 + 2][et4]) = a2;
            *reinterpret_cast<float4*>(&sm->G[gt4 + 3][et4]) = a3;
        }
        __syncthreads();

        // ---- cell update layer 2: writes h2 into S rows 52..102 ----
        for (int c = tid; c < CELLS; c += NTH) {
            int k = c / NB;
            int e = c - k * NB;
            float gi = sm->G[k        ][e] + sm->bs2[k];
            float gf = sm->G[H   + k  ][e] + sm->bs2[H   + k];
            float gg = sm->G[2*H + k  ][e] + sm->bs2[2*H + k];
            float go = sm->G[3*H + k  ][e] + sm->bs2[3*H + k];
            float cc = sm->c2[k][e];
            float cn = sigf(gf) * cc + sigf(gi) * tanh_f(gg);
            float hn = sigf(go) * tanh_f(cn);
            sm->c2[k][e]     = cn;
            sm->S[52 + k][e] = hn;
        }
        __syncthreads();

        // ---- output: out[e] = h2[e] . wlin + blin ----
        if (tid < NB) {
            float acc = sm->blin;
            #pragma unroll 4
            for (int k = 0; k < H; ++k) acc += sm->S[52 + k][tid] * sm->wlin[k];
            sm->outbuf[tid] = acc;
            int b = b0 + tid;
            if (b < BATCH) out[b * NTOT + t] = acc;
        }
        __syncthreads();   // protects outbuf / G reuse across iterations
    }
}

extern "C" void kernel_launch(void* const* d_in, const int* in_sizes, int n_in,
                              void* d_out, int out_size) {
    const float* inputs = (const float*)d_in[0];
    const float* Wih1   = (const float*)d_in[1];
    const float* Whh1   = (const float*)d_in[2];
    const float* bih1   = (const float*)d_in[3];
    const float* bhh1   = (const float*)d_in[4];
    const float* Wih2   = (const float*)d_in[5];
    const float* Whh2   = (const float*)d_in[6];
    const float* bih2   = (const float*)d_in[7];
    const float* bhh2   = (const float*)d_in[8];
    const float* Wlin   = (const float*)d_in[9];
    const float* blin   = (const float*)d_in[10];
    // d_in[11] = future (hardcoded FUT=100)

    cudaFuncSetAttribute(lstm_kernel,
                         cudaFuncAttributeMaxDynamicSharedMemorySize,
                         (int)sizeof(Smem));

    prep_kernel<<<256, 256>>>(inputs);
    lstm_kernel<<<NBLK, NTH, sizeof(Smem)>>>(Wih1, Whh1, bih1, bhh1,
                                             Wih2, Whh2, bih2, bhh2,
                                             Wlin, blin, (float*)d_out);
}